// round 1
// baseline (speedup 1.0000x reference)
#include <cuda_runtime.h>
#include <math.h>

// Problem constants (fixed shapes for this problem)
#define B_   1024
#define U_   1024
#define I_   64
#define G4_  (4 * U_)          // 4096
#define KTOT (U_ + I_)         // 1088
#define BK_  16
#define NKT  (KTOT / BK_)      // 68 k-tiles
#define NKT_X (I_ / BK_)       // first 4 k-tiles come from X, rest from H

// Scratch state (device globals: allocation-free per harness rules)
__device__ float g_h[2][B_ * U_];   // double-buffered hidden state
__device__ float g_c[B_ * U_];      // cell state (updated in place per step)
__device__ float g_p[B_ * I_];      // autoregressive prediction buffer

// ---------------------------------------------------------------------------
// Fused LSTM step: z = [x|h] @ [[Wk];[Wr]] + b, gates, c/h update.
// Block: 128 batch x 64 units (x4 gates). 512 threads, each 8x2x4 = 64 accs.
// ---------------------------------------------------------------------------
#define BM_   128
#define BNU_  64
#define NTHR_ 512

__device__ __forceinline__ float sigf(float x) { return 1.0f / (1.0f + expf(-x)); }

__global__ __launch_bounds__(NTHR_, 1)
void lstm_step(const float* __restrict__ X,   // nullptr -> use g_p (decode)
               int xstride,                   // row stride of X in floats
               int hin_sel,                   // which g_h buffer is input
               const float* __restrict__ Wk,  // [64, 4096]
               const float* __restrict__ Wr,  // [1024, 4096]
               const float* __restrict__ bias)// [4096]
{
    __shared__ float As[BK_][BM_ + 4];     // A tile, k-major, padded
    __shared__ float Ws[BK_][4 * BNU_];    // W tile: col = gate*64 + u

    const float* Xp   = X ? X : g_p;
    const int    xs   = X ? xstride : I_;
    const float* Hin  = g_h[hin_sel];
    float*       Hout = g_h[hin_sel ^ 1];

    const int tid = threadIdx.x;
    const int bm0 = blockIdx.y * BM_;
    const int u0  = blockIdx.x * BNU_;

    // A loader: thread -> (row, 4 consecutive k)
    const int a_row = tid >> 2;            // 0..127
    const int a_kq  = (tid & 3) << 2;      // 0,4,8,12

    const int tmi = tid >> 5;              // 0..15 -> batch sub-tile (8 rows)
    const int tni = tid & 31;              // 0..31 -> unit sub-tile (2 units)

    float acc[4][8][2];
#pragma unroll
    for (int g = 0; g < 4; g++)
#pragma unroll
        for (int i = 0; i < 8; i++) { acc[g][i][0] = 0.f; acc[g][i][1] = 0.f; }

    float4 aReg;
    float4 wReg0, wReg1;

    // ---- global loads (register prefetch) ----
    auto loadA = [&](int kt) -> float4 {
        int kk  = kt * BK_ + a_kq;
        int row = bm0 + a_row;
        if (kt < NKT_X)
            return *(const float4*)(Xp + (long)row * xs + kk);
        else
            return *(const float4*)(Hin + (long)row * U_ + (kk - I_));
    };
    auto loadW = [&](int kt, int s) -> float4 {
        int slot = tid + s * NTHR_;        // 0..1023
        int kl   = slot >> 6;              // 0..15
        int rem  = slot & 63;              // gate*16 + q
        int col  = (rem >> 4) * U_ + u0 + ((rem & 15) << 2);
        int kg   = kt * BK_ + kl;
        const float* src = (kt < NKT_X) ? (Wk + (long)kg * G4_ + col)
                                        : (Wr + (long)(kg - I_) * G4_ + col);
        return *(const float4*)src;
    };
    auto storeA = [&](float4 v) {
        As[a_kq + 0][a_row] = v.x;
        As[a_kq + 1][a_row] = v.y;
        As[a_kq + 2][a_row] = v.z;
        As[a_kq + 3][a_row] = v.w;
    };
    auto storeW = [&](float4 v, int s) {
        int slot = tid + s * NTHR_;
        int kl   = slot >> 6;
        int rem  = slot & 63;
        *(float4*)&Ws[kl][rem << 2] = v;   // (g*64 + q*4) == rem*4
    };

    aReg = loadA(0); wReg0 = loadW(0, 0); wReg1 = loadW(0, 1);
    storeA(aReg); storeW(wReg0, 0); storeW(wReg1, 1);
    __syncthreads();

    for (int kt = 0; kt < NKT; kt++) {
        if (kt + 1 < NKT) {
            aReg  = loadA(kt + 1);
            wReg0 = loadW(kt + 1, 0);
            wReg1 = loadW(kt + 1, 1);
        }
#pragma unroll
        for (int kk = 0; kk < BK_; kk++) {
            float4 a0 = *(const float4*)&As[kk][tmi * 8];
            float4 a1 = *(const float4*)&As[kk][tmi * 8 + 4];
            float av[8] = {a0.x, a0.y, a0.z, a0.w, a1.x, a1.y, a1.z, a1.w};
            float wv[4][2];
#pragma unroll
            for (int g = 0; g < 4; g++) {
                float2 w = *(const float2*)&Ws[kk][g * BNU_ + tni * 2];
                wv[g][0] = w.x; wv[g][1] = w.y;
            }
#pragma unroll
            for (int g = 0; g < 4; g++)
#pragma unroll
                for (int i = 0; i < 8; i++) {
                    acc[g][i][0] += av[i] * wv[g][0];
                    acc[g][i][1] += av[i] * wv[g][1];
                }
        }
        __syncthreads();
        if (kt + 1 < NKT) {
            storeA(aReg); storeW(wReg0, 0); storeW(wReg1, 1);
            __syncthreads();
        }
    }

    // ---- fused gate epilogue ----
#pragma unroll
    for (int j = 0; j < 2; j++) {
        int u  = u0 + tni * 2 + j;
        float bi = bias[u];
        float bf = bias[U_ + u];
        float bg = bias[2 * U_ + u];
        float bo = bias[3 * U_ + u];
#pragma unroll
        for (int i = 0; i < 8; i++) {
            int bm = bm0 + tmi * 8 + i;
            long off = (long)bm * U_ + u;
            float zi = acc[0][i][j] + bi;
            float zf = acc[1][i][j] + bf;
            float zg = acc[2][i][j] + bg;
            float zo = acc[3][i][j] + bo;
            float cn = sigf(zf) * g_c[off] + sigf(zi) * tanhf(zg);
            float hn = sigf(zo) * tanhf(cn);
            g_c[off]  = cn;
            Hout[off] = hn;
        }
    }
}

// ---------------------------------------------------------------------------
// Dense head: p = h @ Wd + bd; also scatters the requested output columns.
// ---------------------------------------------------------------------------
__global__ void pred_kernel(int hsel,
                            const float* __restrict__ Wd,   // [1024, 64]
                            const float* __restrict__ bd,   // [64]
                            float* __restrict__ out,
                            const int* __restrict__ idx,
                            int n_out, int S, int s)
{
    int t = blockIdx.x * blockDim.x + threadIdx.x;   // B_*I_ threads
    int b = t >> 6;
    int j = t & 63;
    const float* hrow = g_h[hsel] + (long)b * U_;
    float acc = 0.f;
#pragma unroll 8
    for (int k = 0; k < U_; k++)
        acc += hrow[k] * Wd[k * I_ + j];
    acc += bd[j];
    g_p[b * I_ + j] = acc;
    for (int jj = 0; jj < n_out; jj++)
        if (idx[jj] == j)
            out[(long)b * S * n_out + s * n_out + jj] = acc;
}

__global__ void init_kernel()
{
    int t = blockIdx.x * blockDim.x + threadIdx.x;
    if (t < B_ * U_) { g_h[0][t] = 0.f; g_c[t] = 0.f; }
}

// ---------------------------------------------------------------------------
extern "C" void kernel_launch(void* const* d_in, const int* in_sizes, int n_in,
                              void* d_out, int out_size)
{
    const float* inputs = (const float*)d_in[0];   // [B, T, I]
    const float* Wk     = (const float*)d_in[1];   // [I, 4U]
    const float* Wr     = (const float*)d_in[2];   // [U, 4U]
    const float* b      = (const float*)d_in[3];   // [4U]
    const float* Wd     = (const float*)d_in[4];   // [U, I]
    const float* bd     = (const float*)d_in[5];   // [I]
    const int*   idx    = (const int*)d_in[6];     // output_indices
    int n_out = in_sizes[6];
    int T     = in_sizes[0] / (B_ * I_);
    int S     = out_size / (B_ * n_out);
    float* out = (float*)d_out;

    init_kernel<<<(B_ * U_ + 255) / 256, 256>>>();

    dim3 grid(U_ / BNU_, B_ / BM_);   // (16, 8) = 128 blocks

    int cur = 0;
    // warmup scan over the input sequence
    for (int t = 0; t < T; t++) {
        lstm_step<<<grid, NTHR_>>>(inputs + (long)t * I_, T * I_, cur, Wk, Wr, b);
        cur ^= 1;
    }
    // first prediction
    pred_kernel<<<(B_ * I_) / 256, 256>>>(cur, Wd, bd, out, idx, n_out, S, 0);
    // autoregressive decode
    for (int s = 1; s < S; s++) {
        lstm_step<<<grid, NTHR_>>>(nullptr, 0, cur, Wk, Wr, b);
        cur ^= 1;
        pred_kernel<<<(B_ * I_) / 256, 256>>>(cur, Wd, bd, out, idx, n_out, S, s);
    }
}

// round 9
// speedup vs baseline: 1.6466x; 1.6466x over previous
#include <cuda_runtime.h>
#include <cuda_bf16.h>
#include <math.h>
#include <stdint.h>

// ---------------- problem constants ----------------
#define B_   1024
#define U_   1024
#define I_   64
#define TMAX 256
#define KSEG 1088              // 64 (x) + 1024 (h)
#define NSTG 51                // 3 segments * 17 stages
#define STG_PER_SEG 17

// ---------------- GEMM tiling ----------------
#define MT   128               // batch rows per CTA
#define NT   256               // gate-cols per CTA (64 units * 4 gates)
#define KC   64                // K per smem stage (64 bf16 = 128B = SW128 row)
#define NTHR 512

#define STAGE_BYTES 49152      // A 16KB + B 32KB
#define S_A_OFF     1024
#define S_TOTAL     (S_A_OFF + 3 * STAGE_BYTES)   // 148480

// ---------------- device scratch (static, allocation-free) ----------------
// weights repacked: row n = u*4+g, col k (0..63 from Wk, 64..1087 from Wr), bf16 hi/lo
__device__ __align__(256) __nv_bfloat16 g_Whi[4096 * KSEG];
__device__ __align__(256) __nv_bfloat16 g_Wlo[4096 * KSEG];
// inputs split to bf16 hi/lo, same [B][T][I] layout
__device__ __align__(256) __nv_bfloat16 g_Xhi[B_ * TMAX * I_];
__device__ __align__(256) __nv_bfloat16 g_Xlo[B_ * TMAX * I_];
// hidden state bf16 hi/lo, double buffered
__device__ __align__(256) __nv_bfloat16 g_Ahh[2][B_ * U_];
__device__ __align__(256) __nv_bfloat16 g_Ahl[2][B_ * U_];
// autoregressive prediction, bf16 hi/lo
__device__ __align__(256) __nv_bfloat16 g_ph[B_ * I_];
__device__ __align__(256) __nv_bfloat16 g_pl[B_ * I_];
// fp32 state
__device__ float g_c[B_ * U_];
__device__ float g_h[B_ * U_];

__device__ __forceinline__ float sigf(float x) { return 1.0f / (1.0f + expf(-x)); }

// ---------------------------------------------------------------------------
// mma.sync LSTM step: z = [x|h] @ W (3-term split-bf16, K_eff = 3264), fused gates.
// Grid: (16 n-tiles, 8 m-tiles) = 128 CTAs, 512 threads (16 warps, 64x32 each).
// ---------------------------------------------------------------------------
__global__ __launch_bounds__(NTHR, 1)
void lstm_step_mma(int t, int T, int hsel, const float* __restrict__ bias)
{
    extern __shared__ char smem[];
    uint32_t sb = (uint32_t)__cvta_generic_to_shared(smem);
    const int tid  = threadIdx.x;
    const int wid  = tid >> 5;
    const int lane = tid & 31;
    const int wm   = wid >> 3;        // 0..1  (64-row m slab)
    const int wn   = wid & 7;         // 0..7  (32-col n slab)
    const int m0   = blockIdx.y * MT;
    const int n0   = blockIdx.x * NT;

    const __nv_bfloat16* xh; const __nv_bfloat16* xl; long xstr;
    if (t >= 0) { xh = g_Xhi + (long)t * I_; xl = g_Xlo + (long)t * I_; xstr = (long)T * I_; }
    else        { xh = g_ph;                 xl = g_pl;                 xstr = I_; }
    const __nv_bfloat16* hh = g_Ahh[hsel];
    const __nv_bfloat16* hl = g_Ahl[hsel];

    // --- stage loader: A tile 128x64 bf16 (16KB) + B tile 256x64 bf16 (32KB) ---
    auto load_stage = [&](int s, int buf) {
        int seg = s / STG_PER_SEG;
        int sis = s - seg * STG_PER_SEG;
        // segment products: 0: Ahi*Whi   1: Alo*Whi   2: Ahi*Wlo
        const __nv_bfloat16* asrc; long astr;
        if (sis == 0) { asrc = (seg == 1) ? xl : xh;                      astr = xstr; }
        else          { asrc = ((seg == 1) ? hl : hh) + (sis - 1) * KC;   astr = U_;  }
        const __nv_bfloat16* bsrc = ((seg == 2) ? g_Wlo : g_Whi) + sis * KC;
        uint32_t ab = sb + S_A_OFF + (uint32_t)buf * STAGE_BYTES;
        uint32_t bb = ab + 16384;
#pragma unroll
        for (int i = 0; i < 2; i++) {               // A: 1024 x 16B
            int idx = tid + i * NTHR;
            int r = idx >> 3, cb = (idx & 7) << 4;
            uint32_t off = (uint32_t)(r * 128 + cb); off ^= (off >> 3) & 0x70;
            const char* src = (const char*)(asrc + (long)(m0 + r) * astr) + cb;
            asm volatile("cp.async.cg.shared.global [%0], [%1], 16;" :: "r"(ab + off), "l"(src));
        }
#pragma unroll
        for (int i = 0; i < 4; i++) {               // B: 2048 x 16B
            int idx = tid + i * NTHR;
            int r = idx >> 3, cb = (idx & 7) << 4;
            uint32_t off = (uint32_t)(r * 128 + cb); off ^= (off >> 3) & 0x70;
            const char* src = (const char*)(bsrc + (long)(n0 + r) * KSEG) + cb;
            asm volatile("cp.async.cg.shared.global [%0], [%1], 16;" :: "r"(bb + off), "l"(src));
        }
        asm volatile("cp.async.commit_group;" ::: "memory");
    };

    float acc[4][4][4];
#pragma unroll
    for (int i = 0; i < 4; i++)
#pragma unroll
        for (int j = 0; j < 4; j++) {
            acc[i][j][0] = 0.f; acc[i][j][1] = 0.f;
            acc[i][j][2] = 0.f; acc[i][j][3] = 0.f;
        }

    load_stage(0, 0);
    load_stage(1, 1);

    for (int s = 0; s < NSTG; s++) {
        int buf = s % 3;
        __syncthreads();                 // everyone done reading buf (s+2)%3 (prev stage)
        if (s + 2 < NSTG) load_stage(s + 2, (s + 2) % 3);
        if (s + 2 < NSTG)      asm volatile("cp.async.wait_group 2;" ::: "memory");
        else if (s + 1 < NSTG) asm volatile("cp.async.wait_group 1;" ::: "memory");
        else                   asm volatile("cp.async.wait_group 0;" ::: "memory");
        __syncthreads();                 // stage s data visible to all warps

        uint32_t ab = sb + S_A_OFF + (uint32_t)buf * STAGE_BYTES;
        uint32_t bb = ab + 16384;
#pragma unroll
        for (int kk = 0; kk < 4; kk++) {
            uint32_t af[4][4];
            uint32_t bf[4][2];
#pragma unroll
            for (int i = 0; i < 4; i++) {
                uint32_t row = (uint32_t)(wm * 64 + i * 16 + (lane & 15));
                uint32_t kb  = (uint32_t)(kk * 32 + ((lane >> 4) << 4));
                uint32_t off = row * 128 + kb; off ^= (off >> 3) & 0x70;
                asm volatile("ldmatrix.sync.aligned.m8n8.x4.shared.b16 {%0,%1,%2,%3}, [%4];"
                    : "=r"(af[i][0]), "=r"(af[i][1]), "=r"(af[i][2]), "=r"(af[i][3])
                    : "r"(ab + off));
            }
#pragma unroll
            for (int jj = 0; jj < 2; jj++) {
                uint32_t nr  = (uint32_t)(wn * 32 + jj * 16 + ((lane >> 4) << 3) + (lane & 7));
                uint32_t kb  = (uint32_t)(kk * 32 + (((lane >> 3) & 1) << 4));
                uint32_t off = nr * 128 + kb; off ^= (off >> 3) & 0x70;
                uint32_t r0, r1, r2, r3;
                asm volatile("ldmatrix.sync.aligned.m8n8.x4.shared.b16 {%0,%1,%2,%3}, [%4];"
                    : "=r"(r0), "=r"(r1), "=r"(r2), "=r"(r3) : "r"(bb + off));
                bf[jj * 2][0] = r0; bf[jj * 2][1] = r1;
                bf[jj * 2 + 1][0] = r2; bf[jj * 2 + 1][1] = r3;
            }
#pragma unroll
            for (int i = 0; i < 4; i++)
#pragma unroll
                for (int j = 0; j < 4; j++)
                    asm volatile(
                        "mma.sync.aligned.m16n8k16.row.col.f32.bf16.bf16.f32 "
                        "{%0,%1,%2,%3}, {%4,%5,%6,%7}, {%8,%9}, {%0,%1,%2,%3};"
                        : "+f"(acc[i][j][0]), "+f"(acc[i][j][1]),
                          "+f"(acc[i][j][2]), "+f"(acc[i][j][3])
                        : "r"(af[i][0]), "r"(af[i][1]), "r"(af[i][2]), "r"(af[i][3]),
                          "r"(bf[j][0]), "r"(bf[j][1]));
        }
    }

    // --- fused gate epilogue straight from accumulators ---
    // c-frag mapping: c0,c1 = (row = lane>>2, cols lp*2, lp*2+1); c2,c3 = row+8.
    // cols n = n0 + wn*32 + j*8 + lp*2 + {0,1};  n = 4u+g  =>  lane pairs (lp even|odd)
    // jointly hold all 4 gates of unit u = n0/4 + wn*8 + j*2 + lp/2.
    {
        const int nsel = hsel ^ 1;
        const int lp = lane & 3;
        const bool ev = (lp & 1) == 0;
#pragma unroll
        for (int i = 0; i < 4; i++)
#pragma unroll
            for (int j = 0; j < 4; j++) {
                float t0 = __shfl_xor_sync(0xffffffffu, acc[i][j][0], 1);
                float t1 = __shfl_xor_sync(0xffffffffu, acc[i][j][1], 1);
                float t2 = __shfl_xor_sync(0xffffffffu, acc[i][j][2], 1);
                float t3 = __shfl_xor_sync(0xffffffffu, acc[i][j][3], 1);
                float zi, zf, zg, zo; int bm;
                if (ev) {   // even lane: own (g0,g1) row r; partner supplies (g2,g3) row r
                    zi = acc[i][j][0]; zf = acc[i][j][1]; zg = t0; zo = t1;
                    bm = m0 + wm * 64 + i * 16 + (lane >> 2);
                } else {    // odd lane: partner (g0,g1) row r+8; own (g2,g3) row r+8
                    zi = t2; zf = t3; zg = acc[i][j][2]; zo = acc[i][j][3];
                    bm = m0 + wm * 64 + i * 16 + (lane >> 2) + 8;
                }
                int u = (n0 >> 2) + wn * 8 + j * 2 + (lp >> 1);
                zi += bias[u];
                zf += bias[U_ + u];
                zg += bias[2 * U_ + u];
                zo += bias[3 * U_ + u];
                long off = (long)bm * U_ + u;
                float cn = sigf(zf) * g_c[off] + sigf(zi) * tanhf(zg);
                float hn = sigf(zo) * tanhf(cn);
                g_c[off] = cn;
                g_h[off] = hn;
                __nv_bfloat16 hhi = __float2bfloat16(hn);
                g_Ahh[nsel][off] = hhi;
                g_Ahl[nsel][off] = __float2bfloat16(hn - __bfloat162float(hhi));
            }
    }
}

// ---------------------------------------------------------------------------
// Dense head: p = h @ Wd + bd; write bf16 hi/lo feedback + scatter outputs.
// ---------------------------------------------------------------------------
__global__ void pred_kernel(const float* __restrict__ Wd, const float* __restrict__ bd,
                            float* __restrict__ out, const int* __restrict__ idx,
                            int n_out, int S, int s)
{
    __shared__ float hs[4][U_];
    const int tid = threadIdx.x;                 // 256
    const int b0 = blockIdx.x * 4;
    for (int i = tid; i < 4 * U_; i += 256) {
        int r = i >> 10, k = i & 1023;
        hs[r][k] = g_h[(long)(b0 + r) * U_ + k];
    }
    __syncthreads();
    const int br = tid >> 6, j = tid & 63;
    const int b = b0 + br;
    float acc = 0.f;
#pragma unroll 8
    for (int k = 0; k < U_; k++)
        acc += hs[br][k] * Wd[k * I_ + j];
    acc += bd[j];
    __nv_bfloat16 hi = __float2bfloat16(acc);
    g_ph[b * I_ + j] = hi;
    g_pl[b * I_ + j] = __float2bfloat16(acc - __bfloat162float(hi));
    for (int jj = 0; jj < n_out; jj++)
        if (idx[jj] == j)
            out[((long)b * S + s) * n_out + jj] = acc;
}

// ---------------------------------------------------------------------------
// One-time conversions (run per launch; deterministic)
// ---------------------------------------------------------------------------
__global__ void conv_w(const float* __restrict__ Wk, const float* __restrict__ Wr)
{
    long i = (long)blockIdx.x * blockDim.x + threadIdx.x;
    if (i >= 4096L * KSEG) return;
    int n = (int)(i / KSEG), k = (int)(i % KSEG);
    int u = n >> 2, g = n & 3;
    float v = (k < I_) ? Wk[(long)k * 4096 + g * U_ + u]
                       : Wr[(long)(k - I_) * 4096 + g * U_ + u];
    __nv_bfloat16 hi = __float2bfloat16(v);
    g_Whi[i] = hi;
    g_Wlo[i] = __float2bfloat16(v - __bfloat162float(hi));
}

__global__ void conv_x(const float* __restrict__ X, long n)
{
    long i = (long)blockIdx.x * blockDim.x + threadIdx.x;
    if (i >= n) return;
    float v = X[i];
    __nv_bfloat16 hi = __float2bfloat16(v);
    g_Xhi[i] = hi;
    g_Xlo[i] = __float2bfloat16(v - __bfloat162float(hi));
}

__global__ void init_state()
{
    int i = blockIdx.x * blockDim.x + threadIdx.x;
    if (i < B_ * U_) {
        g_c[i] = 0.f;
        g_Ahh[0][i] = __float2bfloat16(0.f);
        g_Ahl[0][i] = __float2bfloat16(0.f);
    }
}

// ---------------------------------------------------------------------------
extern "C" void kernel_launch(void* const* d_in, const int* in_sizes, int n_in,
                              void* d_out, int out_size)
{
    const float* inputs = (const float*)d_in[0];   // [B, T, I]
    const float* Wk     = (const float*)d_in[1];   // [I, 4U]
    const float* Wr     = (const float*)d_in[2];   // [U, 4U]
    const float* b      = (const float*)d_in[3];   // [4U]
    const float* Wd     = (const float*)d_in[4];   // [U, I]
    const float* bd     = (const float*)d_in[5];   // [I]
    const int*   idx    = (const int*)d_in[6];     // output_indices
    int n_out = in_sizes[6];
    int T     = in_sizes[0] / (B_ * I_);
    int S     = out_size / (B_ * n_out);
    float* out = (float*)d_out;

    cudaFuncSetAttribute(lstm_step_mma, cudaFuncAttributeMaxDynamicSharedMemorySize, S_TOTAL);

    conv_w<<<(int)((4096L * KSEG + 255) / 256), 256>>>(Wk, Wr);
    conv_x<<<(int)(((long)B_ * T * I_ + 255) / 256), 256>>>(inputs, (long)B_ * T * I_);
    init_state<<<(B_ * U_ + 255) / 256, 256>>>();

    dim3 grid(4 * U_ / NT, B_ / MT);   // (16, 8) = 128 CTAs

    int cur = 0;
    for (int t = 0; t < T; t++) {
        lstm_step_mma<<<grid, NTHR, S_TOTAL>>>(t, T, cur, b);
        cur ^= 1;
    }
    pred_kernel<<<B_ / 4, 256>>>(Wd, bd, out, idx, n_out, S, 0);
    for (int s = 1; s < S; s++) {
        lstm_step_mma<<<grid, NTHR, S_TOTAL>>>(-1, T, cur, b);
        cur ^= 1;
        pred_kernel<<<B_ / 4, 256>>>(Wd, bd, out, idx, n_out, S, s);
    }
}

// round 11
// speedup vs baseline: 1.6708x; 1.0147x over previous
#include <cuda_runtime.h>
#include <cuda_bf16.h>
#include <math.h>
#include <stdint.h>

// ---------------- problem constants ----------------
#define B_   1024
#define U_   1024
#define I_   64
#define TMAX 256
#define KSEG 1088              // 64 (x) + 1024 (h)
#define NSTG 51                // 3 segments * 17 stages
#define STG_PER_SEG 17

// ---------------- GEMM tiling ----------------
#define MT   128               // batch rows per CTA
#define NT   256               // gate-cols per CTA (64 units * 4 gates)
#define KC   64                // K per smem stage (64 bf16 = 128B = SW128 row)
#define NTHR 256               // 8 warps, warp tile 64x64 (2m x 4n)

#define STAGE_BYTES 49152      // A 16KB + B 32KB
#define S_A_OFF     1024
#define S_TOTAL     (S_A_OFF + 3 * STAGE_BYTES)   // 148480

// ---------------- device scratch (static, allocation-free) ----------------
__device__ __align__(256) __nv_bfloat16 g_Whi[4096 * KSEG];
__device__ __align__(256) __nv_bfloat16 g_Wlo[4096 * KSEG];
__device__ __align__(256) __nv_bfloat16 g_Xhi[B_ * TMAX * I_];
__device__ __align__(256) __nv_bfloat16 g_Xlo[B_ * TMAX * I_];
__device__ __align__(256) __nv_bfloat16 g_Ahh[2][B_ * U_];
__device__ __align__(256) __nv_bfloat16 g_Ahl[2][B_ * U_];
__device__ __align__(256) __nv_bfloat16 g_ph[B_ * I_];
__device__ __align__(256) __nv_bfloat16 g_pl[B_ * I_];
__device__ float g_c[B_ * U_];
__device__ float g_h[B_ * U_];

__device__ __forceinline__ float sigf(float x) { return 1.0f / (1.0f + expf(-x)); }

// ---------------------------------------------------------------------------
// mma.sync LSTM step: z = [x|h] @ W (3-term split-bf16, K_eff = 3264), fused gates.
// Grid (16,8) = 128 CTAs. 256 threads, 8 warps: wm=wid>>2 (2 m-slabs of 64),
// wn=wid&3 (4 n-slabs of 64). Double-buffered ldmatrix fragments.
// ---------------------------------------------------------------------------
__global__ __launch_bounds__(NTHR, 1)
void lstm_step_mma(int t, int T, int hsel, const float* __restrict__ bias)
{
    extern __shared__ char smem[];
    uint32_t sb = (uint32_t)__cvta_generic_to_shared(smem);
    const int tid  = threadIdx.x;
    const int wid  = tid >> 5;
    const int lane = tid & 31;
    const int wm   = wid >> 2;        // 0..1
    const int wn   = wid & 3;         // 0..3
    const int m0   = blockIdx.y * MT;
    const int n0   = blockIdx.x * NT;

    const __nv_bfloat16* xh; const __nv_bfloat16* xl; long xstr;
    if (t >= 0) { xh = g_Xhi + (long)t * I_; xl = g_Xlo + (long)t * I_; xstr = (long)T * I_; }
    else        { xh = g_ph;                 xl = g_pl;                 xstr = I_; }
    const __nv_bfloat16* hh = g_Ahh[hsel];
    const __nv_bfloat16* hl = g_Ahl[hsel];

    // --- stage loader: A 128x64 (16KB) + B 256x64 (32KB), 12 cp.async/thread ---
    auto load_stage = [&](int s, int buf) {
        int seg = s / STG_PER_SEG;
        int sis = s - seg * STG_PER_SEG;
        // segments: 0: Ahi*Whi   1: Alo*Whi   2: Ahi*Wlo
        const __nv_bfloat16* asrc; long astr;
        if (sis == 0) { asrc = (seg == 1) ? xl : xh;                      astr = xstr; }
        else          { asrc = ((seg == 1) ? hl : hh) + (sis - 1) * KC;   astr = U_;  }
        const __nv_bfloat16* bsrc = ((seg == 2) ? g_Wlo : g_Whi) + sis * KC;
        uint32_t ab = sb + S_A_OFF + (uint32_t)buf * STAGE_BYTES;
        uint32_t bb = ab + 16384;
#pragma unroll
        for (int i = 0; i < 4; i++) {               // A: 1024 x 16B
            int idx = tid + i * NTHR;
            int r = idx >> 3, cb = (idx & 7) << 4;
            uint32_t off = (uint32_t)(r * 128 + cb); off ^= (off >> 3) & 0x70;
            const char* src = (const char*)(asrc + (long)(m0 + r) * astr) + cb;
            asm volatile("cp.async.cg.shared.global [%0], [%1], 16;" :: "r"(ab + off), "l"(src));
        }
#pragma unroll
        for (int i = 0; i < 8; i++) {               // B: 2048 x 16B
            int idx = tid + i * NTHR;
            int r = idx >> 3, cb = (idx & 7) << 4;
            uint32_t off = (uint32_t)(r * 128 + cb); off ^= (off >> 3) & 0x70;
            const char* src = (const char*)(bsrc + (long)(n0 + r) * KSEG) + cb;
            asm volatile("cp.async.cg.shared.global [%0], [%1], 16;" :: "r"(bb + off), "l"(src));
        }
        asm volatile("cp.async.commit_group;" ::: "memory");
    };

    float acc[4][8][4];
#pragma unroll
    for (int i = 0; i < 4; i++)
#pragma unroll
        for (int j = 0; j < 8; j++) {
            acc[i][j][0] = 0.f; acc[i][j][1] = 0.f;
            acc[i][j][2] = 0.f; acc[i][j][3] = 0.f;
        }

    uint32_t afr[2][4][4];   // [pingpong][m16 tile][frag reg]
    uint32_t bfr[2][8][2];   // [pingpong][n8 tile][frag reg]

    // per-thread constant address parts
    const uint32_t a_row_off = (uint32_t)((wm * 64 + (lane & 15)) * 128 + ((lane >> 4) << 4));
    const uint32_t b_row_off = (uint32_t)((wn * 64 + ((lane >> 4) << 3) + (lane & 7)) * 128
                                          + (((lane >> 3) & 1) << 4));

    auto ldfrag = [&](int kk, int pb, uint32_t ab, uint32_t bb) {
#pragma unroll
        for (int i = 0; i < 4; i++) {
            uint32_t off = a_row_off + (uint32_t)(i * 2048 + kk * 32);
            off ^= (off >> 3) & 0x70;
            asm volatile("ldmatrix.sync.aligned.m8n8.x4.shared.b16 {%0,%1,%2,%3}, [%4];"
                : "=r"(afr[pb][i][0]), "=r"(afr[pb][i][1]),
                  "=r"(afr[pb][i][2]), "=r"(afr[pb][i][3])
                : "r"(ab + off));
        }
#pragma unroll
        for (int jj = 0; jj < 4; jj++) {
            uint32_t off = b_row_off + (uint32_t)(jj * 2048 + kk * 32);
            off ^= (off >> 3) & 0x70;
            uint32_t r0, r1, r2, r3;
            asm volatile("ldmatrix.sync.aligned.m8n8.x4.shared.b16 {%0,%1,%2,%3}, [%4];"
                : "=r"(r0), "=r"(r1), "=r"(r2), "=r"(r3) : "r"(bb + off));
            bfr[pb][jj * 2][0] = r0;     bfr[pb][jj * 2][1] = r1;
            bfr[pb][jj * 2 + 1][0] = r2; bfr[pb][jj * 2 + 1][1] = r3;
        }
    };

    load_stage(0, 0);
    load_stage(1, 1);

    for (int s = 0; s < NSTG; s++) {
        if (s < NSTG - 1) asm volatile("cp.async.wait_group 1;" ::: "memory");
        else              asm volatile("cp.async.wait_group 0;" ::: "memory");
        __syncthreads();                         // stage s visible; buf (s-1)%3 drained
        if (s + 2 < NSTG) load_stage(s + 2, (s + 2) % 3);

        uint32_t ab = sb + S_A_OFF + (uint32_t)(s % 3) * STAGE_BYTES;
        uint32_t bb = ab + 16384;
        ldfrag(0, 0, ab, bb);
#pragma unroll
        for (int kk = 0; kk < 4; kk++) {
            int pb = kk & 1;
            if (kk < 3) ldfrag(kk + 1, pb ^ 1, ab, bb);
#pragma unroll
            for (int i = 0; i < 4; i++)
#pragma unroll
                for (int j = 0; j < 8; j++)
                    asm volatile(
                        "mma.sync.aligned.m16n8k16.row.col.f32.bf16.bf16.f32 "
                        "{%0,%1,%2,%3}, {%4,%5,%6,%7}, {%8,%9}, {%0,%1,%2,%3};"
                        : "+f"(acc[i][j][0]), "+f"(acc[i][j][1]),
                          "+f"(acc[i][j][2]), "+f"(acc[i][j][3])
                        : "r"(afr[pb][i][0]), "r"(afr[pb][i][1]),
                          "r"(afr[pb][i][2]), "r"(afr[pb][i][3]),
                          "r"(bfr[pb][j][0]), "r"(bfr[pb][j][1]));
        }
    }

    // --- fused gate epilogue straight from accumulators ---
    // cols n = n0 + wn*64 + j*8 + lp*2 + {0,1}; n = 4u+g => lane pair (lp even|odd)
    // holds all 4 gates of unit u = n0/4 + wn*16 + j*2 + lp/2.
    {
        const int nsel = hsel ^ 1;
        const int lp = lane & 3;
        const bool ev = (lp & 1) == 0;
#pragma unroll
        for (int i = 0; i < 4; i++)
#pragma unroll
            for (int j = 0; j < 8; j++) {
                float t0 = __shfl_xor_sync(0xffffffffu, acc[i][j][0], 1);
                float t1 = __shfl_xor_sync(0xffffffffu, acc[i][j][1], 1);
                float t2 = __shfl_xor_sync(0xffffffffu, acc[i][j][2], 1);
                float t3 = __shfl_xor_sync(0xffffffffu, acc[i][j][3], 1);
                float zi, zf, zg, zo; int bm;
                if (ev) {   // even lane: own (g0,g1) row r; partner supplies (g2,g3) row r
                    zi = acc[i][j][0]; zf = acc[i][j][1]; zg = t0; zo = t1;
                    bm = m0 + wm * 64 + i * 16 + (lane >> 2);
                } else {    // odd lane: partner (g0,g1) row r+8; own (g2,g3) row r+8
                    zi = t2; zf = t3; zg = acc[i][j][2]; zo = acc[i][j][3];
                    bm = m0 + wm * 64 + i * 16 + (lane >> 2) + 8;
                }
                int u = (n0 >> 2) + wn * 16 + j * 2 + (lp >> 1);
                zi += bias[u];
                zf += bias[U_ + u];
                zg += bias[2 * U_ + u];
                zo += bias[3 * U_ + u];
                long off = (long)bm * U_ + u;
                float cn = sigf(zf) * g_c[off] + sigf(zi) * tanhf(zg);
                float hn = sigf(zo) * tanhf(cn);
                g_c[off] = cn;
                g_h[off] = hn;
                __nv_bfloat16 hhi = __float2bfloat16(hn);
                g_Ahh[nsel][off] = hhi;
                g_Ahl[nsel][off] = __float2bfloat16(hn - __bfloat162float(hhi));
            }
    }
}

// ---------------------------------------------------------------------------
// Dense head: p = h @ Wd + bd; write bf16 hi/lo feedback + scatter outputs.
// ---------------------------------------------------------------------------
__global__ void pred_kernel(const float* __restrict__ Wd, const float* __restrict__ bd,
                            float* __restrict__ out, const int* __restrict__ idx,
                            int n_out, int S, int s)
{
    __shared__ float hs[4][U_];
    const int tid = threadIdx.x;                 // 256
    const int b0 = blockIdx.x * 4;
    for (int i = tid; i < 4 * U_; i += 256) {
        int r = i >> 10, k = i & 1023;
        hs[r][k] = g_h[(long)(b0 + r) * U_ + k];
    }
    __syncthreads();
    const int br = tid >> 6, j = tid & 63;
    const int b = b0 + br;
    float acc = 0.f;
#pragma unroll 8
    for (int k = 0; k < U_; k++)
        acc += hs[br][k] * Wd[k * I_ + j];
    acc += bd[j];
    __nv_bfloat16 hi = __float2bfloat16(acc);
    g_ph[b * I_ + j] = hi;
    g_pl[b * I_ + j] = __float2bfloat16(acc - __bfloat162float(hi));
    for (int jj = 0; jj < n_out; jj++)
        if (idx[jj] == j)
            out[((long)b * S + s) * n_out + jj] = acc;
}

// ---------------------------------------------------------------------------
// One-time conversions (run per launch; deterministic)
// ---------------------------------------------------------------------------
__global__ void conv_w(const float* __restrict__ Wk, const float* __restrict__ Wr)
{
    long i = (long)blockIdx.x * blockDim.x + threadIdx.x;
    if (i >= 4096L * KSEG) return;
    int n = (int)(i / KSEG), k = (int)(i % KSEG);
    int u = n >> 2, g = n & 3;
    float v = (k < I_) ? Wk[(long)k * 4096 + g * U_ + u]
                       : Wr[(long)(k - I_) * 4096 + g * U_ + u];
    __nv_bfloat16 hi = __float2bfloat16(v);
    g_Whi[i] = hi;
    g_Wlo[i] = __float2bfloat16(v - __bfloat162float(hi));
}

__global__ void conv_x(const float* __restrict__ X, long n)
{
    long i = (long)blockIdx.x * blockDim.x + threadIdx.x;
    if (i >= n) return;
    float v = X[i];
    __nv_bfloat16 hi = __float2bfloat16(v);
    g_Xhi[i] = hi;
    g_Xlo[i] = __float2bfloat16(v - __bfloat162float(hi));
}

__global__ void init_state()
{
    int i = blockIdx.x * blockDim.x + threadIdx.x;
    if (i < B_ * U_) {
        g_c[i] = 0.f;
        g_Ahh[0][i] = __float2bfloat16(0.f);
        g_Ahl[0][i] = __float2bfloat16(0.f);
    }
}

// ---------------------------------------------------------------------------
extern "C" void kernel_launch(void* const* d_in, const int* in_sizes, int n_in,
                              void* d_out, int out_size)
{
    const float* inputs = (const float*)d_in[0];   // [B, T, I]
    const float* Wk     = (const float*)d_in[1];   // [I, 4U]
    const float* Wr     = (const float*)d_in[2];   // [U, 4U]
    const float* b      = (const float*)d_in[3];   // [4U]
    const float* Wd     = (const float*)d_in[4];   // [U, I]
    const float* bd     = (const float*)d_in[5];   // [I]
    const int*   idx    = (const int*)d_in[6];     // output_indices
    int n_out = in_sizes[6];
    int T     = in_sizes[0] / (B_ * I_);
    int S     = out_size / (B_ * n_out);
    float* out = (float*)d_out;

    cudaFuncSetAttribute(lstm_step_mma, cudaFuncAttributeMaxDynamicSharedMemorySize, S_TOTAL);

    conv_w<<<(int)((4096L * KSEG + 255) / 256), 256>>>(Wk, Wr);
    conv_x<<<(int)(((long)B_ * T * I_ + 255) / 256), 256>>>(inputs, (long)B_ * T * I_);
    init_state<<<(B_ * U_ + 255) / 256, 256>>>();

    dim3 grid(4 * U_ / NT, B_ / MT);   // (16, 8) = 128 CTAs

    int cur = 0;
    for (int t = 0; t < T; t++) {
        lstm_step_mma<<<grid, NTHR, S_TOTAL>>>(t, T, cur, b);
        cur ^= 1;
    }
    pred_kernel<<<B_ / 4, 256>>>(Wd, bd, out, idx, n_out, S, 0);
    for (int s = 1; s < S; s++) {
        lstm_step_mma<<<grid, NTHR, S_TOTAL>>>(-1, T, cur, b);
        cur ^= 1;
        pred_kernel<<<B_ / 4, 256>>>(Wd, bd, out, idx, n_out, S, s);
    }
}

// round 12
// speedup vs baseline: 1.8914x; 1.1321x over previous
#include <cuda_runtime.h>
#include <cuda_bf16.h>
#include <math.h>
#include <stdint.h>

// ---------------- problem constants ----------------
#define B_   1024
#define U_   1024
#define I_   64
#define TMAX 256
#define KSEG 1088              // 64 (x) + 1024 (h)
#define NSTG 51                // 3 segments * 17 stages
#define STG_PER_SEG 17

// ---------------- GEMM tiling ----------------
#define MT   128               // batch rows per CTA
#define NT   128               // gate-cols per CTA (32 units * 4 gates)
#define KC   64                // K per smem stage (64 bf16 = 128B = SW128 row)
#define NTHR 256               // 8 warps, warp tile 64x32 (2m x 4n)

#define STAGE_BYTES 32768      // A 16KB + B 16KB
#define S_A_OFF     1024
#define S_TOTAL     (S_A_OFF + 3 * STAGE_BYTES)   // 99328 -> 2 CTAs/SM

// ---------------- device scratch (static, allocation-free) ----------------
__device__ __align__(256) __nv_bfloat16 g_Whi[4096 * KSEG];
__device__ __align__(256) __nv_bfloat16 g_Wlo[4096 * KSEG];
__device__ __align__(256) __nv_bfloat16 g_Xhi[B_ * TMAX * I_];
__device__ __align__(256) __nv_bfloat16 g_Xlo[B_ * TMAX * I_];
__device__ __align__(256) __nv_bfloat16 g_Ahh[2][B_ * U_];
__device__ __align__(256) __nv_bfloat16 g_Ahl[2][B_ * U_];
__device__ __align__(256) __nv_bfloat16 g_ph[B_ * I_];
__device__ __align__(256) __nv_bfloat16 g_pl[B_ * I_];
__device__ float g_c[B_ * U_];
__device__ float g_h[B_ * U_];

__device__ __forceinline__ float sigf(float x) { return 1.0f / (1.0f + expf(-x)); }

// ---------------------------------------------------------------------------
// mma.sync LSTM step: z = [x|h] @ W (3-term split-bf16, K_eff = 3264), fused gates.
// Grid (32,8) = 256 CTAs, 2 CTAs/SM. 256 threads, 8 warps: wm=wid>>2 (2 m-slabs
// of 64), wn=wid&3 (4 n-slabs of 32). Warp tile 64x32.
// ---------------------------------------------------------------------------
__global__ __launch_bounds__(NTHR, 2)
void lstm_step_mma(int t, int T, int hsel, const float* __restrict__ bias)
{
    extern __shared__ char smem[];
    uint32_t sb = (uint32_t)__cvta_generic_to_shared(smem);
    const int tid  = threadIdx.x;
    const int wid  = tid >> 5;
    const int lane = tid & 31;
    const int wm   = wid >> 2;        // 0..1
    const int wn   = wid & 3;         // 0..3
    const int m0   = blockIdx.y * MT;
    const int n0   = blockIdx.x * NT;

    const __nv_bfloat16* xh; const __nv_bfloat16* xl; long xstr;
    if (t >= 0) { xh = g_Xhi + (long)t * I_; xl = g_Xlo + (long)t * I_; xstr = (long)T * I_; }
    else        { xh = g_ph;                 xl = g_pl;                 xstr = I_; }
    const __nv_bfloat16* hh = g_Ahh[hsel];
    const __nv_bfloat16* hl = g_Ahl[hsel];

    // --- stage loader: A 128x64 (16KB) + B 128x64 (16KB), 8 cp.async/thread ---
    auto load_stage = [&](int s, int buf) {
        int seg = s / STG_PER_SEG;
        int sis = s - seg * STG_PER_SEG;
        // segments: 0: Ahi*Whi   1: Alo*Whi   2: Ahi*Wlo
        const __nv_bfloat16* asrc; long astr;
        if (sis == 0) { asrc = (seg == 1) ? xl : xh;                      astr = xstr; }
        else          { asrc = ((seg == 1) ? hl : hh) + (sis - 1) * KC;   astr = U_;  }
        const __nv_bfloat16* bsrc = ((seg == 2) ? g_Wlo : g_Whi) + sis * KC;
        uint32_t ab = sb + S_A_OFF + (uint32_t)buf * STAGE_BYTES;
        uint32_t bb = ab + 16384;
#pragma unroll
        for (int i = 0; i < 4; i++) {               // A: 1024 x 16B
            int idx = tid + i * NTHR;
            int r = idx >> 3, cb = (idx & 7) << 4;
            uint32_t off = (uint32_t)(r * 128 + cb); off ^= (off >> 3) & 0x70;
            const char* src = (const char*)(asrc + (long)(m0 + r) * astr) + cb;
            asm volatile("cp.async.cg.shared.global [%0], [%1], 16;" :: "r"(ab + off), "l"(src));
        }
#pragma unroll
        for (int i = 0; i < 4; i++) {               // B: 1024 x 16B
            int idx = tid + i * NTHR;
            int r = idx >> 3, cb = (idx & 7) << 4;
            uint32_t off = (uint32_t)(r * 128 + cb); off ^= (off >> 3) & 0x70;
            const char* src = (const char*)(bsrc + (long)(n0 + r) * KSEG) + cb;
            asm volatile("cp.async.cg.shared.global [%0], [%1], 16;" :: "r"(bb + off), "l"(src));
        }
        asm volatile("cp.async.commit_group;" ::: "memory");
    };

    float acc[4][4][4];
#pragma unroll
    for (int i = 0; i < 4; i++)
#pragma unroll
        for (int j = 0; j < 4; j++) {
            acc[i][j][0] = 0.f; acc[i][j][1] = 0.f;
            acc[i][j][2] = 0.f; acc[i][j][3] = 0.f;
        }

    uint32_t afr[4][4];     // 4 m16 tiles
    uint32_t bfr[4][2];     // 4 n8 tiles

    // per-thread constant address parts
    const uint32_t a_row_off = (uint32_t)((wm * 64 + (lane & 15)) * 128 + ((lane >> 4) << 4));
    const uint32_t b_row_off = (uint32_t)((wn * 32 + ((lane >> 4) << 3) + (lane & 7)) * 128
                                          + (((lane >> 3) & 1) << 4));

    load_stage(0, 0);
    load_stage(1, 1);

    for (int s = 0; s < NSTG; s++) {
        if (s < NSTG - 1) asm volatile("cp.async.wait_group 1;" ::: "memory");
        else              asm volatile("cp.async.wait_group 0;" ::: "memory");
        __syncthreads();                         // stage s visible; buf (s-1)%3 drained
        if (s + 2 < NSTG) load_stage(s + 2, (s + 2) % 3);

        uint32_t ab = sb + S_A_OFF + (uint32_t)(s % 3) * STAGE_BYTES;
        uint32_t bb = ab + 16384;
#pragma unroll
        for (int kk = 0; kk < 4; kk++) {
#pragma unroll
            for (int i = 0; i < 4; i++) {
                uint32_t off = a_row_off + (uint32_t)(i * 2048 + kk * 32);
                off ^= (off >> 3) & 0x70;
                asm volatile("ldmatrix.sync.aligned.m8n8.x4.shared.b16 {%0,%1,%2,%3}, [%4];"
                    : "=r"(afr[i][0]), "=r"(afr[i][1]), "=r"(afr[i][2]), "=r"(afr[i][3])
                    : "r"(ab + off));
            }
#pragma unroll
            for (int jj = 0; jj < 2; jj++) {
                uint32_t off = b_row_off + (uint32_t)(jj * 2048 + kk * 32);
                off ^= (off >> 3) & 0x70;
                uint32_t r0, r1, r2, r3;
                asm volatile("ldmatrix.sync.aligned.m8n8.x4.shared.b16 {%0,%1,%2,%3}, [%4];"
                    : "=r"(r0), "=r"(r1), "=r"(r2), "=r"(r3) : "r"(bb + off));
                bfr[jj * 2][0] = r0;     bfr[jj * 2][1] = r1;
                bfr[jj * 2 + 1][0] = r2; bfr[jj * 2 + 1][1] = r3;
            }
#pragma unroll
            for (int i = 0; i < 4; i++)
#pragma unroll
                for (int j = 0; j < 4; j++)
                    asm volatile(
                        "mma.sync.aligned.m16n8k16.row.col.f32.bf16.bf16.f32 "
                        "{%0,%1,%2,%3}, {%4,%5,%6,%7}, {%8,%9}, {%0,%1,%2,%3};"
                        : "+f"(acc[i][j][0]), "+f"(acc[i][j][1]),
                          "+f"(acc[i][j][2]), "+f"(acc[i][j][3])
                        : "r"(afr[i][0]), "r"(afr[i][1]),
                          "r"(afr[i][2]), "r"(afr[i][3]),
                          "r"(bfr[j][0]), "r"(bfr[j][1]));
        }
    }

    // --- fused gate epilogue straight from accumulators ---
    // cols n = n0 + wn*32 + j*8 + lp*2 + {0,1}; n = 4u+g => lane pair (lp even|odd)
    // holds all 4 gates of unit u = n0/4 + wn*8 + j*2 + lp/2.
    {
        const int nsel = hsel ^ 1;
        const int lp = lane & 3;
        const bool ev = (lp & 1) == 0;
#pragma unroll
        for (int i = 0; i < 4; i++)
#pragma unroll
            for (int j = 0; j < 4; j++) {
                float t0 = __shfl_xor_sync(0xffffffffu, acc[i][j][0], 1);
                float t1 = __shfl_xor_sync(0xffffffffu, acc[i][j][1], 1);
                float t2 = __shfl_xor_sync(0xffffffffu, acc[i][j][2], 1);
                float t3 = __shfl_xor_sync(0xffffffffu, acc[i][j][3], 1);
                float zi, zf, zg, zo; int bm;
                if (ev) {   // even lane: own (g0,g1) row r; partner supplies (g2,g3) row r
                    zi = acc[i][j][0]; zf = acc[i][j][1]; zg = t0; zo = t1;
                    bm = m0 + wm * 64 + i * 16 + (lane >> 2);
                } else {    // odd lane: partner (g0,g1) row r+8; own (g2,g3) row r+8
                    zi = t2; zf = t3; zg = acc[i][j][2]; zo = acc[i][j][3];
                    bm = m0 + wm * 64 + i * 16 + (lane >> 2) + 8;
                }
                int u = (n0 >> 2) + wn * 8 + j * 2 + (lp >> 1);
                zi += bias[u];
                zf += bias[U_ + u];
                zg += bias[2 * U_ + u];
                zo += bias[3 * U_ + u];
                long off = (long)bm * U_ + u;
                float cn = sigf(zf) * g_c[off] + sigf(zi) * tanhf(zg);
                float hn = sigf(zo) * tanhf(cn);
                g_c[off] = cn;
                g_h[off] = hn;
                __nv_bfloat16 hhi = __float2bfloat16(hn);
                g_Ahh[nsel][off] = hhi;
                g_Ahl[nsel][off] = __float2bfloat16(hn - __bfloat162float(hhi));
            }
    }
}

// ---------------------------------------------------------------------------
// Dense head: p = h @ Wd + bd; write bf16 hi/lo feedback + scatter outputs.
// ---------------------------------------------------------------------------
__global__ void pred_kernel(const float* __restrict__ Wd, const float* __restrict__ bd,
                            float* __restrict__ out, const int* __restrict__ idx,
                            int n_out, int S, int s)
{
    __shared__ float hs[4][U_];
    const int tid = threadIdx.x;                 // 256
    const int b0 = blockIdx.x * 4;
    for (int i = tid; i < 4 * U_; i += 256) {
        int r = i >> 10, k = i & 1023;
        hs[r][k] = g_h[(long)(b0 + r) * U_ + k];
    }
    __syncthreads();
    const int br = tid >> 6, j = tid & 63;
    const int b = b0 + br;
    float acc = 0.f;
#pragma unroll 8
    for (int k = 0; k < U_; k++)
        acc += hs[br][k] * Wd[k * I_ + j];
    acc += bd[j];
    __nv_bfloat16 hi = __float2bfloat16(acc);
    g_ph[b * I_ + j] = hi;
    g_pl[b * I_ + j] = __float2bfloat16(acc - __bfloat162float(hi));
    for (int jj = 0; jj < n_out; jj++)
        if (idx[jj] == j)
            out[((long)b * S + s) * n_out + jj] = acc;
}

// ---------------------------------------------------------------------------
// One-time conversions (run per launch; deterministic)
// ---------------------------------------------------------------------------
__global__ void conv_w(const float* __restrict__ Wk, const float* __restrict__ Wr)
{
    long i = (long)blockIdx.x * blockDim.x + threadIdx.x;
    if (i >= 4096L * KSEG) return;
    int n = (int)(i / KSEG), k = (int)(i % KSEG);
    int u = n >> 2, g = n & 3;
    float v = (k < I_) ? Wk[(long)k * 4096 + g * U_ + u]
                       : Wr[(long)(k - I_) * 4096 + g * U_ + u];
    __nv_bfloat16 hi = __float2bfloat16(v);
    g_Whi[i] = hi;
    g_Wlo[i] = __float2bfloat16(v - __bfloat162float(hi));
}

__global__ void conv_x(const float* __restrict__ X, long n)
{
    long i = (long)blockIdx.x * blockDim.x + threadIdx.x;
    if (i >= n) return;
    float v = X[i];
    __nv_bfloat16 hi = __float2bfloat16(v);
    g_Xhi[i] = hi;
    g_Xlo[i] = __float2bfloat16(v - __bfloat162float(hi));
}

__global__ void init_state()
{
    int i = blockIdx.x * blockDim.x + threadIdx.x;
    if (i < B_ * U_) {
        g_c[i] = 0.f;
        g_Ahh[0][i] = __float2bfloat16(0.f);
        g_Ahl[0][i] = __float2bfloat16(0.f);
    }
}

// ---------------------------------------------------------------------------
extern "C" void kernel_launch(void* const* d_in, const int* in_sizes, int n_in,
                              void* d_out, int out_size)
{
    const float* inputs = (const float*)d_in[0];   // [B, T, I]
    const float* Wk     = (const float*)d_in[1];   // [I, 4U]
    const float* Wr     = (const float*)d_in[2];   // [U, 4U]
    const float* b      = (const float*)d_in[3];   // [4U]
    const float* Wd     = (const float*)d_in[4];   // [U, I]
    const float* bd     = (const float*)d_in[5];   // [I]
    const int*   idx    = (const int*)d_in[6];     // output_indices
    int n_out = in_sizes[6];
    int T     = in_sizes[0] / (B_ * I_);
    int S     = out_size / (B_ * n_out);
    float* out = (float*)d_out;

    cudaFuncSetAttribute(lstm_step_mma, cudaFuncAttributeMaxDynamicSharedMemorySize, S_TOTAL);

    conv_w<<<(int)((4096L * KSEG + 255) / 256), 256>>>(Wk, Wr);
    conv_x<<<(int)(((long)B_ * T * I_ + 255) / 256), 256>>>(inputs, (long)B_ * T * I_);
    init_state<<<(B_ * U_ + 255) / 256, 256>>>();

    dim3 grid(4 * U_ / NT, B_ / MT);   // (32, 8) = 256 CTAs

    int cur = 0;
    for (int t = 0; t < T; t++) {
        lstm_step_mma<<<grid, NTHR, S_TOTAL>>>(t, T, cur, b);
        cur ^= 1;
    }
    pred_kernel<<<B_ / 4, 256>>>(Wd, bd, out, idx, n_out, S, 0);
    for (int s = 1; s < S; s++) {
        lstm_step_mma<<<grid, NTHR, S_TOTAL>>>(-1, T, cur, b);
        cur ^= 1;
        pred_kernel<<<B_ / 4, 256>>>(Wd, bd, out, idx, n_out, S, s);
    }
}